// round 15
// baseline (speedup 1.0000x reference)
#include <cuda_runtime.h>
#include <cstdint>

// LSTMTagger: 262144 sequential steps, H=128 (512 gate rows), I=2.
// R14 = R13 (8-CTA cluster, k-split-2, in-warp gate transpose) + chain trims:
//  (a) EX2-domain gate weights: rows pre-scaled by -log2e (gate2: -2log2e),
//      so sigma = rcp(1+ex2(s)) -- removes the __expf-internal FMUL from the
//      gate-activation chain. Gate2 post-transform 2*sigma-1 unchanged.
//  (b) c-path tanh via one FMUL: tanh(c) = 1 - 2*rcp(1+ex2(c*2log2e)).
//  (c) remote-gemv h loads batched into registers before the FMA chain (MLP).
// Comms unchanged: plain cluster arrives (R11 finding), store-immediately,
// own-half partial in the S2/flight window. Full fp32. Double-buffered h.

#define L_SEQ   262144
#define H_DIM   128
#define SLICE   16
#define CN      8
#define NT      128
#define CHUNK   1024
#define RCOLS   56      // remote cols per thread (112/2)
#define OCOLS   8       // own cols per thread (16/2)
#define N_ARRV  112     // 7 peers x 16 lanes per phase

#define NLOG2E  (-1.4426950408889634f)   // -log2(e)
#define TLOG2E  ( 2.8853900817779268f)   //  2*log2(e)

__device__ __forceinline__ float sigmoid_f(float x) {   // outputs only
    return __fdividef(1.0f, 1.0f + __expf(-x));
}

__device__ __forceinline__ uint32_t smem_u32(const void* ptr) {
    uint32_t a;
    asm("{ .reg .u64 t; cvta.to.shared.u64 t, %1; cvt.u32.u64 %0, t; }"
        : "=r"(a) : "l"(ptr));
    return a;
}
__device__ __forceinline__ uint32_t cluster_rank_() {
    uint32_t v; asm("mov.u32 %0, %%cluster_ctarank;" : "=r"(v)); return v;
}
__device__ __forceinline__ uint32_t mapa_u32(uint32_t addr, uint32_t rk) {
    uint32_t v;
    asm("mapa.shared::cluster.u32 %0, %1, %2;" : "=r"(v) : "r"(addr), "r"(rk));
    return v;
}
__device__ __forceinline__ void sts_cluster_f32(uint32_t raddr, float v) {
    asm volatile("st.shared::cluster.f32 [%0], %1;"
                 :: "r"(raddr), "f"(v) : "memory");
}
__device__ __forceinline__ void mbar_arrive_cluster(uint32_t raddr) {
    asm volatile("mbarrier.arrive.shared::cluster.b64 _, [%0];"
                 :: "r"(raddr) : "memory");
}
__device__ __forceinline__ void mbar_init(uint32_t addr, uint32_t count) {
    asm volatile("mbarrier.init.shared.b64 [%0], %1;"
                 :: "r"(addr), "r"(count) : "memory");
}
__device__ __forceinline__ void mbar_wait_parity_acq_cluster(uint32_t addr,
                                                             uint32_t parity) {
    uint32_t done;
    asm volatile(
        "{\n\t.reg .pred p;\n\t"
        "mbarrier.try_wait.parity.acquire.cluster.shared::cta.b64 p, [%1], %2;\n\t"
        "selp.b32 %0, 1, 0, p;\n\t}"
        : "=r"(done) : "r"(addr), "r"(parity) : "memory");
    if (!done) {
        asm volatile(
            "{\n\t.reg .pred P1;\n\t"
            "WL_%=:\n\t"
            "mbarrier.try_wait.parity.acquire.cluster.shared::cta.b64 P1, [%0], %1, 0x989680;\n\t"
            "@P1 bra.uni WD_%=;\n\t"
            "bra.uni WL_%=;\n\t"
            "WD_%=:\n\t}"
            :: "r"(addr), "r"(parity) : "memory");
    }
}
#define CLUSTER_SYNC_() do { \
    asm volatile("barrier.cluster.arrive.aligned;" ::: "memory"); \
    asm volatile("barrier.cluster.wait.aligned;" ::: "memory"); \
} while (0)

__global__ void __launch_bounds__(NT, 1) __cluster_dims__(CN, 1, 1)
lstm_r14_kernel(const float* __restrict__ sentence,
                const float* __restrict__ W_ih,
                const float* __restrict__ W_hh,
                const float* __restrict__ b_ih,
                const float* __restrict__ b_hh,
                const float* __restrict__ W_out,
                const float* __restrict__ b_out,
                float* __restrict__ out)
{
    __shared__ alignas(8)  unsigned long long mbar;
    __shared__ alignas(16) float hbuf[2][H_DIM];
    __shared__ alignas(16) float xbuf[CHUNK * 2];

    const int r     = threadIdx.x;    // 0..127
    const int lane  = r & 31;
    const int w     = r >> 5;         // warp id 0..3
    const int sub   = lane & 3;       // h sub-index within warp
    const int slot  = lane >> 2;      // 0..7: (gate, kpart) AND peer group
    const int gate  = slot & 3;
    const int kpart = slot >> 2;      // 0 or 1
    const uint32_t rank = cluster_rank_();

    const int hidx = (int)rank * SLICE + 4 * w + sub;  // this lane's h index
    const int gr   = gate * H_DIM + hidx;              // gate row

    // EX2-domain scaling: rows scaled by -log2e (gate2 by -2log2e) so that
    // ex2(s) = e^{-g} (resp. e^{-2g}); sigma = rcp(1+ex2(s)); gate2 post-
    // transform a = 2*sigma - 1 = tanh(g).
    const float scW    = (gate == 2) ? 2.0f * NLOG2E : NLOG2E;
    const float act_sc = (gate == 2) ? 2.0f : 1.0f;
    const float act_of = (gate == 2) ? -1.0f : 0.0f;

    // Affine term only on kpart 0 (k-combine sums the two halves).
    const float wih0 = (kpart == 0) ? scW * W_ih[2 * gr + 0] : 0.0f;
    const float wih1 = (kpart == 0) ? scW * W_ih[2 * gr + 1] : 0.0f;
    const float br   = (kpart == 0) ? scW * (b_ih[gr] + b_hh[gr]) : 0.0f;

    // Column windows (actual h column = permuted index & 127):
    const int KBASE = (int)rank * SLICE + SLICE + kpart * RCOLS;
    const int OWNB  = (int)rank * SLICE + kpart * OCOLS;

    float Wr[RCOLS], Wo[OCOLS];
    {
        const float* wrow = W_hh + gr * H_DIM;
#pragma unroll
        for (int jj = 0; jj < RCOLS; ++jj)
            Wr[jj] = scW * wrow[(KBASE + jj) & (H_DIM - 1)];
#pragma unroll
        for (int j = 0; j < OCOLS; ++j)
            Wo[j] = scW * wrow[OWNB + j];
    }

    // init
    if (r < H_DIM) { hbuf[0][r] = 0.0f; hbuf[1][r] = 0.0f; }
    const uint32_t bar_addr = smem_u32(&mbar);
    const uint32_t hb_addr  = smem_u32(&hbuf[0][0]);
    if (r == 0) mbar_init(bar_addr, N_ARRV);
    __syncthreads();
    CLUSTER_SYNC_();

    // slot s targets peer CTA (rank+s)&7; slot 0 = local
    const uint32_t peer     = (rank + (uint32_t)slot) & (CN - 1);
    const uint32_t peer_h   = mapa_u32(hb_addr,  peer);
    const uint32_t peer_bar = mapa_u32(bar_addr, peer);
    const uint32_t my_off   = (uint32_t)hidx * 4u;
    const bool is_remote    = (slot != 0);

    float c_reg = 0.0f;               // redundant across the 8 slots
    float part  = 0.0f;               // own-half partial (h(0)=0)

    for (int t0 = 0; t0 < L_SEQ; t0 += CHUNK) {
        {   // refill x chunk (2048 floats = 512 float4)
            const float4* src = (const float4*)(sentence + 2 * t0);
            float4* dst = (float4*)xbuf;
#pragma unroll
            for (int j = 0; j < 4; ++j) dst[r + j * NT] = src[r + j * NT];
        }
        __syncthreads();

#pragma unroll 1
        for (int ti = 0; ti < CHUNK; ++ti) {
            const int t = t0 + ti;

            // affine + own partial before the wait (no hbuf dependence)
            const float x0 = xbuf[2 * ti + 0];
            const float x1 = xbuf[2 * ti + 1];
            float acc0 = fmaf(wih0, x0, br) + part;
            float acc1 = wih1 * x1;
            float acc2 = 0.0f, acc3 = 0.0f;

            // wait for remote slices of h(t); t=0 uses zeros
            if (t != 0) mbar_wait_parity_acq_cluster(bar_addr, (uint32_t)((t - 1) & 1));

            // remote 56 cols: batch-load all 14 float4 first (MLP), then FMA
            {
                const float* hr = &hbuf[t & 1][0];
                float4 hv[RCOLS / 4];
#pragma unroll
                for (int q = 0; q < RCOLS / 4; ++q) {
                    const int col = (KBASE + 4 * q) & (H_DIM - 1);
                    hv[q] = *(const float4*)(hr + col);
                }
#pragma unroll
                for (int q = 0; q < RCOLS / 4; ++q) {
                    acc0 = fmaf(Wr[4 * q + 0], hv[q].x, acc0);
                    acc1 = fmaf(Wr[4 * q + 1], hv[q].y, acc1);
                    acc2 = fmaf(Wr[4 * q + 2], hv[q].z, acc2);
                    acc3 = fmaf(Wr[4 * q + 3], hv[q].w, acc3);
                }
            }
            float s = (acc0 + acc2) + (acc1 + acc3);

            // k-combine: lanes l and l^16 are same gate/sub, different kpart
            s += __shfl_xor_sync(0xffffffffu, s, 16);

            // sigma = rcp(1 + ex2(s))  [EX2-domain weights], then gate-2
            // post-transform (branchless)
            float a = __fdividef(1.0f, 1.0f + exp2f(s));
            a = fmaf(a, act_sc, act_of);

            // gate transpose: gate g's value lives at lane 4*g + sub
            const float iv = __shfl_sync(0xffffffffu, a, sub);
            const float fv = __shfl_sync(0xffffffffu, a, 4 + sub);
            const float gv = __shfl_sync(0xffffffffu, a, 8 + sub);
            const float ov = __shfl_sync(0xffffffffu, a, 12 + sub);

            // c/h redundantly in all 8 slots (identical values)
            c_reg = fmaf(fv, c_reg, iv * gv);
            // tanh(c) = 1 - 2*rcp(1 + e^{2c}), e^{2c} = ex2(c*2log2e)
            const float ec = exp2f(c_reg * TLOG2E);
            const float th = 1.0f - __fdividef(2.0f, 1.0f + ec);
            const float h  = ov * th;

            // store IMMEDIATELY, fanout parallel across slots (WAR-safe:
            // peer's next wait collects arrivals issued after each warp's
            // shfl-synced reads of the target buffer)
            const int wb = (t + 1) & 1;
            if (is_remote) {
                sts_cluster_f32(peer_h + (uint32_t)(wb * H_DIM * 4) + my_off, h);
                mbar_arrive_cluster(peer_bar);
            } else {
                hbuf[wb][hidx] = h;                        // local slice
            }

            // overlap window (DSMEM in flight): publish local slice, then
            // own-half partial of g(t+1)
            __syncthreads();                               // S2
            {
                const float4* h4 = (const float4*)(&hbuf[wb][OWNB]);
                float p0 = 0.0f, p1 = 0.0f, p2 = 0.0f, p3 = 0.0f;
#pragma unroll
                for (int q = 0; q < OCOLS / 4; ++q) {
                    const float4 hv2 = h4[q];
                    p0 = fmaf(Wo[4 * q + 0], hv2.x, p0);
                    p1 = fmaf(Wo[4 * q + 1], hv2.y, p1);
                    p2 = fmaf(Wo[4 * q + 2], hv2.z, p2);
                    p3 = fmaf(Wo[4 * q + 3], hv2.w, p3);
                }
                part = (p0 + p2) + (p1 + p3);
            }
        }
    }

    // final wait: collect last-step arrivals (phase (L-1)&1 = 1)
    mbar_wait_parity_acq_cluster(bar_addr, (uint32_t)((L_SEQ - 1) & 1));

    // Outputs: out[0]=sigmoid(h.W_out+b), out[1..128]=h_n, out[129..256]=c_n
    if (slot == 0) out[1 + H_DIM + hidx] = c_reg;  // 16 c values per CTA
    if (rank == 0) {
        const float* hf = &hbuf[L_SEQ & 1][0];     // = hbuf[0]
        if (r < H_DIM) out[1 + r] = hf[r];
        if (r < 32) {
            float s = 0.0f;
#pragma unroll
            for (int m = 0; m < 4; ++m)
                s = fmaf(hf[4 * r + m], W_out[4 * r + m], s);
#pragma unroll
            for (int off = 16; off > 0; off >>= 1)
                s += __shfl_xor_sync(0xffffffffu, s, off);
            if (r == 0) out[0] = sigmoid_f(s + b_out[0]);
        }
    }
    CLUSTER_SYNC_();
}

extern "C" void kernel_launch(void* const* d_in, const int* in_sizes, int n_in,
                              void* d_out, int out_size)
{
    const float* sentence = (const float*)d_in[0];
    const float* W_ih     = (const float*)d_in[1];
    const float* W_hh     = (const float*)d_in[2];
    const float* b_ih     = (const float*)d_in[3];
    const float* b_hh     = (const float*)d_in[4];
    const float* W_out    = (const float*)d_in[5];
    const float* b_out    = (const float*)d_in[6];
    float* out            = (float*)d_out;

    lstm_r14_kernel<<<CN, NT>>>(
        sentence, W_ih, W_hh, b_ih, b_hh, W_out, b_out, out);
}

// round 16
// speedup vs baseline: 1.0125x; 1.0125x over previous
#include <cuda_runtime.h>
#include <cstdint>

// LSTMTagger: 262144 sequential steps, H=128 (512 gate rows), I=2.
// R15 = R13 numerics EXACTLY (R14's EX2-domain rewrite degraded rel_err
// 1200x to 8.9e-4, nearly failing, with no speedup -- reverted), keeping
// only R14's numerics-neutral load batching:
//   8-CTA cluster (SLICE=16), 128 thr/CTA, k-split-2 + in-warp gate
//   transpose; gate-2 via 2*sigma(2g)-1 with exactly x2-scaled weights;
//   remote-gemv h loads batched into regs before the FMA chain (MLP);
//   plain cluster arrives (R11), store-immediately (R6 lesson), own-half
//   partial inside the S2/DSMEM-flight window.
// Full fp32, __expf activations (proven ~7e-7 path). Double-buffered h.

#define L_SEQ   262144
#define H_DIM   128
#define SLICE   16
#define CN      8
#define NT      128
#define CHUNK   1024
#define RCOLS   56      // remote cols per thread (112/2)
#define OCOLS   8       // own cols per thread (16/2)
#define N_ARRV  112     // 7 peers x 16 lanes per phase

__device__ __forceinline__ float sigmoid_f(float x) {
    return __fdividef(1.0f, 1.0f + __expf(-x));
}
__device__ __forceinline__ float tanh_f(float x) {
    return 1.0f - __fdividef(2.0f, 1.0f + __expf(2.0f * x));
}

__device__ __forceinline__ uint32_t smem_u32(const void* ptr) {
    uint32_t a;
    asm("{ .reg .u64 t; cvta.to.shared.u64 t, %1; cvt.u32.u64 %0, t; }"
        : "=r"(a) : "l"(ptr));
    return a;
}
__device__ __forceinline__ uint32_t cluster_rank_() {
    uint32_t v; asm("mov.u32 %0, %%cluster_ctarank;" : "=r"(v)); return v;
}
__device__ __forceinline__ uint32_t mapa_u32(uint32_t addr, uint32_t rk) {
    uint32_t v;
    asm("mapa.shared::cluster.u32 %0, %1, %2;" : "=r"(v) : "r"(addr), "r"(rk));
    return v;
}
__device__ __forceinline__ void sts_cluster_f32(uint32_t raddr, float v) {
    asm volatile("st.shared::cluster.f32 [%0], %1;"
                 :: "r"(raddr), "f"(v) : "memory");
}
__device__ __forceinline__ void mbar_arrive_cluster(uint32_t raddr) {
    asm volatile("mbarrier.arrive.shared::cluster.b64 _, [%0];"
                 :: "r"(raddr) : "memory");
}
__device__ __forceinline__ void mbar_init(uint32_t addr, uint32_t count) {
    asm volatile("mbarrier.init.shared.b64 [%0], %1;"
                 :: "r"(addr), "r"(count) : "memory");
}
__device__ __forceinline__ void mbar_wait_parity_acq_cluster(uint32_t addr,
                                                             uint32_t parity) {
    uint32_t done;
    asm volatile(
        "{\n\t.reg .pred p;\n\t"
        "mbarrier.try_wait.parity.acquire.cluster.shared::cta.b64 p, [%1], %2;\n\t"
        "selp.b32 %0, 1, 0, p;\n\t}"
        : "=r"(done) : "r"(addr), "r"(parity) : "memory");
    if (!done) {
        asm volatile(
            "{\n\t.reg .pred P1;\n\t"
            "WL_%=:\n\t"
            "mbarrier.try_wait.parity.acquire.cluster.shared::cta.b64 P1, [%0], %1, 0x989680;\n\t"
            "@P1 bra.uni WD_%=;\n\t"
            "bra.uni WL_%=;\n\t"
            "WD_%=:\n\t}"
            :: "r"(addr), "r"(parity) : "memory");
    }
}
#define CLUSTER_SYNC_() do { \
    asm volatile("barrier.cluster.arrive.aligned;" ::: "memory"); \
    asm volatile("barrier.cluster.wait.aligned;" ::: "memory"); \
} while (0)

__global__ void __launch_bounds__(NT, 1) __cluster_dims__(CN, 1, 1)
lstm_r15_kernel(const float* __restrict__ sentence,
                const float* __restrict__ W_ih,
                const float* __restrict__ W_hh,
                const float* __restrict__ b_ih,
                const float* __restrict__ b_hh,
                const float* __restrict__ W_out,
                const float* __restrict__ b_out,
                float* __restrict__ out)
{
    __shared__ alignas(8)  unsigned long long mbar;
    __shared__ alignas(16) float hbuf[2][H_DIM];
    __shared__ alignas(16) float xbuf[CHUNK * 2];

    const int r     = threadIdx.x;    // 0..127
    const int lane  = r & 31;
    const int w     = r >> 5;         // warp id 0..3
    const int sub   = lane & 3;       // h sub-index within warp
    const int slot  = lane >> 2;      // 0..7: (gate, kpart) AND peer group
    const int gate  = slot & 3;
    const int kpart = slot >> 2;      // 0 or 1
    const uint32_t rank = cluster_rank_();

    const int hidx = (int)rank * SLICE + 4 * w + sub;  // this lane's h index
    const int gr   = gate * H_DIM + hidx;              // gate row

    // Gate-2 rows scaled by 2 (EXACT power of two): tanh(g) = 2*sigma(2g)-1.
    const float scW    = (gate == 2) ? 2.0f : 1.0f;
    const float act_sc = (gate == 2) ? 2.0f : 1.0f;
    const float act_of = (gate == 2) ? -1.0f : 0.0f;

    // Affine term only on kpart 0 (k-combine sums the two halves).
    const float wih0 = (kpart == 0) ? scW * W_ih[2 * gr + 0] : 0.0f;
    const float wih1 = (kpart == 0) ? scW * W_ih[2 * gr + 1] : 0.0f;
    const float br   = (kpart == 0) ? scW * (b_ih[gr] + b_hh[gr]) : 0.0f;

    // Column windows (actual h column = permuted index & 127):
    const int KBASE = (int)rank * SLICE + SLICE + kpart * RCOLS;
    const int OWNB  = (int)rank * SLICE + kpart * OCOLS;

    float Wr[RCOLS], Wo[OCOLS];
    {
        const float* wrow = W_hh + gr * H_DIM;
#pragma unroll
        for (int jj = 0; jj < RCOLS; ++jj)
            Wr[jj] = scW * wrow[(KBASE + jj) & (H_DIM - 1)];
#pragma unroll
        for (int j = 0; j < OCOLS; ++j)
            Wo[j] = scW * wrow[OWNB + j];
    }

    // init
    if (r < H_DIM) { hbuf[0][r] = 0.0f; hbuf[1][r] = 0.0f; }
    const uint32_t bar_addr = smem_u32(&mbar);
    const uint32_t hb_addr  = smem_u32(&hbuf[0][0]);
    if (r == 0) mbar_init(bar_addr, N_ARRV);
    __syncthreads();
    CLUSTER_SYNC_();

    // slot s targets peer CTA (rank+s)&7; slot 0 = local
    const uint32_t peer     = (rank + (uint32_t)slot) & (CN - 1);
    const uint32_t peer_h   = mapa_u32(hb_addr,  peer);
    const uint32_t peer_bar = mapa_u32(bar_addr, peer);
    const uint32_t my_off   = (uint32_t)hidx * 4u;
    const bool is_remote    = (slot != 0);

    float c_reg = 0.0f;               // redundant across the 8 slots
    float part  = 0.0f;               // own-half partial (h(0)=0)

    for (int t0 = 0; t0 < L_SEQ; t0 += CHUNK) {
        {   // refill x chunk (2048 floats = 512 float4)
            const float4* src = (const float4*)(sentence + 2 * t0);
            float4* dst = (float4*)xbuf;
#pragma unroll
            for (int j = 0; j < 4; ++j) dst[r + j * NT] = src[r + j * NT];
        }
        __syncthreads();

#pragma unroll 1
        for (int ti = 0; ti < CHUNK; ++ti) {
            const int t = t0 + ti;

            // affine + own partial before the wait (no hbuf dependence)
            const float2 xv = *(const float2*)(xbuf + 2 * ti);
            float acc0 = fmaf(wih0, xv.x, br) + part;
            float acc1 = wih1 * xv.y;
            float acc2 = 0.0f, acc3 = 0.0f;

            // wait for remote slices of h(t); t=0 uses zeros
            if (t != 0) mbar_wait_parity_acq_cluster(bar_addr, (uint32_t)((t - 1) & 1));

            // remote 56 cols: batch-load all 14 float4 first (MLP), then the
            // FMA chain in R13's exact accumulation order (bit-identical).
            {
                const float* hr = &hbuf[t & 1][0];
                float4 hv[RCOLS / 4];
#pragma unroll
                for (int q = 0; q < RCOLS / 4; ++q) {
                    const int col = (KBASE + 4 * q) & (H_DIM - 1);
                    hv[q] = *(const float4*)(hr + col);
                }
#pragma unroll
                for (int q = 0; q < RCOLS / 4; ++q) {
                    acc0 = fmaf(Wr[4 * q + 0], hv[q].x, acc0);
                    acc1 = fmaf(Wr[4 * q + 1], hv[q].y, acc1);
                    acc2 = fmaf(Wr[4 * q + 2], hv[q].z, acc2);
                    acc3 = fmaf(Wr[4 * q + 3], hv[q].w, acc3);
                }
            }
            float s = (acc0 + acc2) + (acc1 + acc3);

            // k-combine: lanes l and l^16 are same gate/sub, different kpart
            s += __shfl_xor_sync(0xffffffffu, s, 16);

            // uniform activation + gate-2 post-transform (branchless)
            float a = sigmoid_f(s);
            a = fmaf(a, act_sc, act_of);

            // gate transpose: gate g's value lives at lane 4*g + sub
            const float iv = __shfl_sync(0xffffffffu, a, sub);
            const float fv = __shfl_sync(0xffffffffu, a, 4 + sub);
            const float gv = __shfl_sync(0xffffffffu, a, 8 + sub);
            const float ov = __shfl_sync(0xffffffffu, a, 12 + sub);

            // c/h redundantly in all 8 slots (identical values)
            c_reg = fmaf(fv, c_reg, iv * gv);
            const float h = ov * tanh_f(c_reg);

            // store IMMEDIATELY, fanout parallel across slots (WAR-safe:
            // peer's next wait collects arrivals issued after each warp's
            // shfl-synced reads of the target buffer)
            const int wb = (t + 1) & 1;
            if (is_remote) {
                sts_cluster_f32(peer_h + (uint32_t)(wb * H_DIM * 4) + my_off, h);
                mbar_arrive_cluster(peer_bar);
            } else {
                hbuf[wb][hidx] = h;                        // local slice
            }

            // overlap window (DSMEM in flight): publish local slice, then
            // own-half partial of g(t+1)
            __syncthreads();                               // S2
            {
                const float4* h4 = (const float4*)(&hbuf[wb][OWNB]);
                float p0 = 0.0f, p1 = 0.0f, p2 = 0.0f, p3 = 0.0f;
#pragma unroll
                for (int q = 0; q < OCOLS / 4; ++q) {
                    const float4 hv2 = h4[q];
                    p0 = fmaf(Wo[4 * q + 0], hv2.x, p0);
                    p1 = fmaf(Wo[4 * q + 1], hv2.y, p1);
                    p2 = fmaf(Wo[4 * q + 2], hv2.z, p2);
                    p3 = fmaf(Wo[4 * q + 3], hv2.w, p3);
                }
                part = (p0 + p2) + (p1 + p3);
            }
        }
    }

    // final wait: collect last-step arrivals (phase (L-1)&1 = 1)
    mbar_wait_parity_acq_cluster(bar_addr, (uint32_t)((L_SEQ - 1) & 1));

    // Outputs: out[0]=sigmoid(h.W_out+b), out[1..128]=h_n, out[129..256]=c_n
    if (slot == 0) out[1 + H_DIM + hidx] = c_reg;  // 16 c values per CTA
    if (rank == 0) {
        const float* hf = &hbuf[L_SEQ & 1][0];     // = hbuf[0]
        if (r < H_DIM) out[1 + r] = hf[r];
        if (r < 32) {
            float s2 = 0.0f;
#pragma unroll
            for (int m = 0; m < 4; ++m)
                s2 = fmaf(hf[4 * r + m], W_out[4 * r + m], s2);
#pragma unroll
            for (int off = 16; off > 0; off >>= 1)
                s2 += __shfl_xor_sync(0xffffffffu, s2, off);
            if (r == 0) out[0] = sigmoid_f(s2 + b_out[0]);
        }
    }
    CLUSTER_SYNC_();
}

extern "C" void kernel_launch(void* const* d_in, const int* in_sizes, int n_in,
                              void* d_out, int out_size)
{
    const float* sentence = (const float*)d_in[0];
    const float* W_ih     = (const float*)d_in[1];
    const float* W_hh     = (const float*)d_in[2];
    const float* b_ih     = (const float*)d_in[3];
    const float* b_hh     = (const float*)d_in[4];
    const float* W_out    = (const float*)d_in[5];
    const float* b_out    = (const float*)d_in[6];
    float* out            = (float*)d_out;

    lstm_r15_kernel<<<CN, NT>>>(
        sentence, W_ih, W_hh, b_ih, b_hh, W_out, b_out, out);
}